// round 11
// baseline (speedup 1.0000x reference)
#include <cuda_runtime.h>
#include <cuda_bf16.h>
#include <math.h>
#include <stdint.h>

#define B_   2
#define S_   1024
#define E_   2048
#define NH_  16
#define DH_  128
#define EPS_ 1e-6f
#define NEC  16
#define ECH  384          // 6144 / 16, 6 sub-tiles of 64
#define NSUB 6

#define FMA2(d, a, b)  asm("fma.rn.f32x2 %0, %1, %2, %0;" : "+l"(d) : "l"(a), "l"(b))
#define PACK2(d, x)    asm("mov.b64 %0, {%1, %1};" : "=l"(d) : "f"(x))

__device__ __forceinline__ void cpa16(uint32_t dst, const void* src) {
    asm volatile("cp.async.ca.shared.global [%0], [%1], 16;" :: "r"(dst), "l"(src));
}
__device__ __forceinline__ void cpa_commit() { asm volatile("cp.async.commit_group;"); }

// ---------------- warp-MMA helpers (sm_80-era PTX: safe under compute_103) ----------------
static __device__ __forceinline__ uint32_t pack_bf2(float x0, float x1) {
    uint32_t r; asm("cvt.rn.bf16x2.f32 %0, %1, %2;" : "=r"(r) : "f"(x1), "f"(x0)); return r;
}
static __device__ __forceinline__ float lo_f(uint32_t p) { return __uint_as_float(p << 16); }
static __device__ __forceinline__ float hi_f(uint32_t p) { return __uint_as_float(p & 0xffff0000u); }

#define LDSM4(r, a) \
    asm volatile("ldmatrix.sync.aligned.m8n8.x4.shared.b16 {%0,%1,%2,%3}, [%4];" \
        : "=r"((r)[0]), "=r"((r)[1]), "=r"((r)[2]), "=r"((r)[3]) : "r"(a))
#define LDSM4T(r, a) \
    asm volatile("ldmatrix.sync.aligned.m8n8.x4.trans.shared.b16 {%0,%1,%2,%3}, [%4];" \
        : "=r"((r)[0]), "=r"((r)[1]), "=r"((r)[2]), "=r"((r)[3]) : "r"(a))

static __device__ __forceinline__ void mma16816(float* c, const uint32_t* a, const uint32_t* b) {
    asm volatile("mma.sync.aligned.m16n8k16.row.col.f32.bf16.bf16.f32 "
        "{%0,%1,%2,%3}, {%4,%5,%6,%7}, {%8,%9}, {%0,%1,%2,%3};"
        : "+f"(c[0]), "+f"(c[1]), "+f"(c[2]), "+f"(c[3])
        : "r"(a[0]), "r"(a[1]), "r"(a[2]), "r"(a[3]), "r"(b[0]), "r"(b[1]));
}

__device__ float g_part[2 * NEC * B_ * NH_ * S_];
__device__ float g_a [B_ * NH_ * S_];
__device__ float g_rm[B_ * NH_ * S_];
__device__ float g_nl[B_ * NH_ * S_];

// ============== Kernel 1: gates, static double-buffer, single-wave grid ==============
__global__ __launch_bounds__(256) void gates_partial_k(
    const float* __restrict__ q, const float* __restrict__ k, const float* __restrict__ v,
    const float* __restrict__ Wi, const float* __restrict__ Wf)
{
    __shared__ float Xs[2][64 * 68];
    __shared__ float Ws[2][64 * 32];
    const int rt = blockIdx.x, ec = blockIdx.y;
    const int b = rt >> 4, s0 = (rt & 15) << 6, t = threadIdx.x;
    const int rgrp = t >> 3, hgrp = t & 7;

    auto pf = [&](int sub, int bufi) {
        const int e0 = ec * ECH + sub * 64;
        const float* xp = (e0 < E_) ? q : (e0 < 2 * E_) ? k : v;
        const int col0 = e0 & (E_ - 1);
        float* xd = Xs[bufi];
        float* wd = Ws[bufi];
        #pragma unroll
        for (int c = 0; c < 4; ++c) {
            int idx = t + c * 256, r = idx >> 4, q4 = (idx & 15) * 4;
            cpa16((uint32_t)__cvta_generic_to_shared(xd + r * 68 + q4),
                  xp + ((size_t)(b * S_ + s0 + r)) * E_ + col0 + q4);
        }
        #pragma unroll
        for (int c = 0; c < 2; ++c) {
            int idx = t + c * 256, ee = idx >> 3, cc = idx & 7, eg = e0 + ee;
            const float* src = (cc < 4) ? (Wi + eg * 16 + cc * 4)
                                        : (Wf + eg * 16 + (cc - 4) * 4);
            cpa16((uint32_t)__cvta_generic_to_shared(wd + ee * 32 + cc * 4), src);
        }
        cpa_commit();
    };

    unsigned long long acc2[2][2] = {};
    pf(0, 0);
    #pragma unroll 1
    for (int sub = 0; sub < NSUB; ++sub) {
        const int bufi = sub & 1;
        if (sub < NSUB - 1) {
            pf(sub + 1, bufi ^ 1);
            asm volatile("cp.async.wait_group 1;");
        } else {
            asm volatile("cp.async.wait_group 0;");
        }
        __syncthreads();
        const float* xs = Xs[bufi];
        const float* ws = Ws[bufi];
        #pragma unroll 8
        for (int ee = 0; ee < 64; ++ee) {
            unsigned long long xp2[2];
            #pragma unroll
            for (int m = 0; m < 2; ++m) { float xv = xs[(rgrp * 2 + m) * 68 + ee]; PACK2(xp2[m], xv); }
            ulonglong2 wv = *(const ulonglong2*)(ws + ee * 32 + hgrp * 4);
            #pragma unroll
            for (int m = 0; m < 2; ++m) { FMA2(acc2[m][0], xp2[m], wv.x); FMA2(acc2[m][1], xp2[m], wv.y); }
        }
        __syncthreads();
    }
    #pragma unroll
    for (int m = 0; m < 2; ++m) {
        int s = s0 + rgrp * 2 + m;
        #pragma unroll
        for (int p = 0; p < 2; ++p) {
            float2 u = *(float2*)&acc2[m][p];
            #pragma unroll
            for (int hh = 0; hh < 2; ++hh) {
                int hcol = hgrp * 4 + p * 2 + hh;
                g_part[(((hcol >> 4) * NEC + ec) * (B_ * NH_) + b * NH_ + (hcol & 15)) * S_ + s] = hh ? u.y : u.x;
            }
        }
    }
}

// ============== Kernel 2: scans ==============
__global__ __launch_bounds__(1024, 1) void scan_k(const float* __restrict__ bi, const float* __restrict__ bf)
{
    __shared__ float buf[1024];
    const int bh = blockIdx.x, t = threadIdx.x, h = bh & 15;
    float ig = bi[h], fg = bf[h];
    #pragma unroll
    for (int ec = 0; ec < NEC; ++ec) {
        ig += g_part[((0 * NEC + ec) * (B_ * NH_) + bh) * S_ + t];
        fg += g_part[((1 * NEC + ec) * (B_ * NH_) + bh) * S_ + t];
    }
    float lf = fminf(fg, 0.f) - log1pf(expf(-fabsf(fg)));
    float x = lf;
    buf[t] = x; __syncthreads();
    for (int off = 1; off < 1024; off <<= 1) {
        float y = (t >= off) ? buf[t - off] : 0.f; __syncthreads();
        x += y; buf[t] = x; __syncthreads();
    }
    float cum = x, a = ig - cum;
    x = a; buf[t] = x; __syncthreads();
    for (int off = 1; off < 1024; off <<= 1) {
        float y = (t >= off) ? buf[t - off] : -3.4e38f; __syncthreads();
        x = fmaxf(x, y); buf[t] = x; __syncthreads();
    }
    g_a [bh * S_ + t] = a;
    g_rm[bh * S_ + t] = x;
    g_nl[bh * S_ + t] = expf(-(cum + x));
}

// ============== Kernel 3: HMMA bf16 attention, 64-wide tiles, 2 syncs/tile ==============
#define LDH  136
#define SM_QHI 0
#define SM_QLO 34816
#define SM_KHI 69632
#define SM_KLO 87040
#define SM_VHI 104448
#define SM_VLO 121856
#define SM_RMS 139264
#define SM_ERS 139776
#define SM_WCS 140288
#define SM_BYTES 140800

__global__ __launch_bounds__(256, 1) void attn_k(
    const float* __restrict__ q, const float* __restrict__ k,
    const float* __restrict__ v, const float* __restrict__ lnsc,
    float* __restrict__ out)
{
    extern __shared__ char smc[];
    const uint32_t smb = (uint32_t)__cvta_generic_to_shared(smc);
    float* rmS = (float*)(smc + SM_RMS);
    float* erS = (float*)(smc + SM_ERS);
    float* wcS = (float*)(smc + SM_WCS);

    const int bh = blockIdx.x;
    const int b  = bh >> 4, h = bh & 15;
    const int ri = 7 - (int)blockIdx.y;      // heavy CTAs first
    const int i0 = ri << 7;
    const int t  = threadIdx.x;
    const int w  = t >> 5, lane = t & 31;
    const int gid = lane >> 2, tig = lane & 3;
    const float scale = 0.08838834764831845f;

    // ---- Q load: fold scale, bf16 hi/lo split into padded row-major smem ----
    {
        const float* qb = q + ((size_t)(b * S_ + i0)) * E_ + h * DH_;
        #pragma unroll
        for (int it = 0; it < 16; ++it) {
            int idx = t + it * 256;
            int r = idx >> 5, d4 = (idx & 31) * 4;
            float4 x = *(const float4*)(qb + (size_t)r * E_ + d4);
            x.x *= scale; x.y *= scale; x.z *= scale; x.w *= scale;
            uint32_t h01 = pack_bf2(x.x, x.y), h23 = pack_bf2(x.z, x.w);
            uint32_t l01 = pack_bf2(x.x - lo_f(h01), x.y - hi_f(h01));
            uint32_t l23 = pack_bf2(x.z - lo_f(h23), x.w - hi_f(h23));
            uint32_t bo = (uint32_t)(r * LDH + d4) * 2;
            *(uint2*)(smc + SM_QHI + bo) = make_uint2(h01, h23);
            *(uint2*)(smc + SM_QLO + bo) = make_uint2(l01, l23);
        }
        if (t < 128) rmS[t] = g_rm[bh * S_ + i0 + t];
    }
    __syncthreads();

    // ---- cache Q fragments in registers (A-operand layout) ----
    uint32_t qh[8][4], ql[8][4];
    {
        uint32_t rowq = (uint32_t)(w * 16 + (lane & 7) + 8 * ((lane >> 3) & 1));
        #pragma unroll
        for (int kk = 0; kk < 8; ++kk) {
            uint32_t off = (rowq * LDH + kk * 16 + 8 * (lane >> 4)) * 2;
            LDSM4(qh[kk], smb + SM_QHI + off);
            LDSM4(ql[kk], smb + SM_QLO + off);
        }
    }

    float hacc[16][4];
    #pragma unroll
    for (int n = 0; n < 16; ++n)
        #pragma unroll
        for (int e = 0; e < 4; ++e) hacc[n][e] = 0.f;
    float suma = 0.f, sumb = 0.f;

    const int rowa = i0 + w * 16 + gid;
    const int rowb = rowa + 8;
    const int nj = 2 * ri + 2;

    for (int jt = 0; jt < nj; ++jt) {
        const int j0 = jt << 6;
        __syncthreads();   // prev tile's K/V/table readers done
        // ---- K,V tiles: split hi/lo ----
        {
            const float* kb = k + ((size_t)(b * S_ + j0)) * E_ + h * DH_;
            const float* vb = v + ((size_t)(b * S_ + j0)) * E_ + h * DH_;
            #pragma unroll
            for (int it = 0; it < 8; ++it) {
                int idx = t + it * 256;
                int r = idx >> 5, d4 = (idx & 31) * 4;
                uint32_t bo = (uint32_t)(r * LDH + d4) * 2;
                float4 x = *(const float4*)(kb + (size_t)r * E_ + d4);
                uint32_t h01 = pack_bf2(x.x, x.y), h23 = pack_bf2(x.z, x.w);
                uint32_t l01 = pack_bf2(x.x - lo_f(h01), x.y - hi_f(h01));
                uint32_t l23 = pack_bf2(x.z - lo_f(h23), x.w - hi_f(h23));
                *(uint2*)(smc + SM_KHI + bo) = make_uint2(h01, h23);
                *(uint2*)(smc + SM_KLO + bo) = make_uint2(l01, l23);
                float4 y = *(const float4*)(vb + (size_t)r * E_ + d4);
                uint32_t g01 = pack_bf2(y.x, y.y), g23 = pack_bf2(y.z, y.w);
                uint32_t m01 = pack_bf2(y.x - lo_f(g01), y.y - hi_f(g01));
                uint32_t m23 = pack_bf2(y.z - lo_f(g23), y.w - hi_f(g23));
                *(uint2*)(smc + SM_VHI + bo) = make_uint2(g01, g23);
                *(uint2*)(smc + SM_VLO + bo) = make_uint2(m01, m23);
            }
        }
        // ---- exp tables from direct global reads (same phase, no extra barrier) ----
        if (t < 128) {
            const float* ga = g_a + bh * S_ + j0;
            float m0 = -3.4e38f;
            #pragma unroll 8
            for (int c = 0; c < 64; ++c) m0 = fmaxf(m0, ga[c]);
            if (t < 64) wcS[t] = __expf(ga[t] - m0);
            erS[t] = __expf(fminf(m0 - rmS[t], 80.f));
        }
        __syncthreads();

        // ---- QK: S = Q K^T (3 compensated MMAs) ----
        float sacc[8][4];
        #pragma unroll
        for (int n = 0; n < 8; ++n)
            #pragma unroll
            for (int e = 0; e < 4; ++e) sacc[n][e] = 0.f;
        {
            uint32_t rowk = (uint32_t)((lane & 7) + 8 * (lane >> 4));
            uint32_t colk = (uint32_t)(8 * ((lane >> 3) & 1));
            #pragma unroll
            for (int kk = 0; kk < 8; ++kk) {
                #pragma unroll
                for (int np = 0; np < 4; ++np) {
                    uint32_t off = ((np * 16 + rowk) * LDH + kk * 16 + colk) * 2;
                    uint32_t bhf[4], blf[4];
                    LDSM4(bhf, smb + SM_KHI + off);
                    LDSM4(blf, smb + SM_KLO + off);
                    mma16816(sacc[2 * np],     qh[kk], bhf);
                    mma16816(sacc[2 * np],     qh[kk], blf);
                    mma16816(sacc[2 * np],     ql[kk], bhf);
                    mma16816(sacc[2 * np + 1], qh[kk], bhf + 2);
                    mma16816(sacc[2 * np + 1], qh[kk], blf + 2);
                    mma16816(sacc[2 * np + 1], ql[kk], bhf + 2);
                }
            }
        }

        // ---- S -> P, causal mask, rowsums ----
        const float era = erS[w * 16 + gid];
        const float erb = erS[w * 16 + gid + 8];
        #pragma unroll
        for (int n = 0; n < 8; ++n) {
            const int cbase = n * 8 + 2 * tig;
            const int c0 = j0 + cbase, c1 = c0 + 1;
            const float w0 = wcS[cbase], w1 = wcS[cbase + 1];
            float p0 = (c0 <= rowa) ? sacc[n][0] * w0 * era : 0.f;
            float p1 = (c1 <= rowa) ? sacc[n][1] * w1 * era : 0.f;
            float p2 = (c0 <= rowb) ? sacc[n][2] * w0 * erb : 0.f;
            float p3 = (c1 <= rowb) ? sacc[n][3] * w1 * erb : 0.f;
            suma += p0 + p1; sumb += p2 + p3;
            sacc[n][0] = p0; sacc[n][1] = p1; sacc[n][2] = p2; sacc[n][3] = p3;
        }

        // ---- AV: H += P V (3 compensated MMAs) ----
        {
            uint32_t rowv = (uint32_t)((lane & 7) + 8 * ((lane >> 3) & 1));
            uint32_t colv = (uint32_t)(8 * (lane >> 4));
            #pragma unroll
            for (int kk = 0; kk < 4; ++kk) {
                uint32_t pah[4], pal[4];
                pah[0] = pack_bf2(sacc[2*kk][0],   sacc[2*kk][1]);
                pah[1] = pack_bf2(sacc[2*kk][2],   sacc[2*kk][3]);
                pah[2] = pack_bf2(sacc[2*kk+1][0], sacc[2*kk+1][1]);
                pah[3] = pack_bf2(sacc[2*kk+1][2], sacc[2*kk+1][3]);
                pal[0] = pack_bf2(sacc[2*kk][0]   - lo_f(pah[0]), sacc[2*kk][1]   - hi_f(pah[0]));
                pal[1] = pack_bf2(sacc[2*kk][2]   - lo_f(pah[1]), sacc[2*kk][3]   - hi_f(pah[1]));
                pal[2] = pack_bf2(sacc[2*kk+1][0] - lo_f(pah[2]), sacc[2*kk+1][1] - hi_f(pah[2]));
                pal[3] = pack_bf2(sacc[2*kk+1][2] - lo_f(pah[3]), sacc[2*kk+1][3] - hi_f(pah[3]));
                #pragma unroll
                for (int np = 0; np < 8; ++np) {
                    uint32_t off = ((kk * 16 + rowv) * LDH + np * 16 + colv) * 2;
                    uint32_t bvh[4], bvl[4];
                    LDSM4T(bvh, smb + SM_VHI + off);
                    LDSM4T(bvl, smb + SM_VLO + off);
                    mma16816(hacc[2 * np],     pah, bvh);
                    mma16816(hacc[2 * np],     pah, bvl);
                    mma16816(hacc[2 * np],     pal, bvh);
                    mma16816(hacc[2 * np + 1], pah, bvh + 2);
                    mma16816(hacc[2 * np + 1], pah, bvl + 2);
                    mma16816(hacc[2 * np + 1], pal, bvh + 2);
                }
            }
        }
    }

    // ---- epilogue ----
    suma += __shfl_xor_sync(0xffffffffu, suma, 1);
    suma += __shfl_xor_sync(0xffffffffu, suma, 2);
    sumb += __shfl_xor_sync(0xffffffffu, sumb, 1);
    sumb += __shfl_xor_sync(0xffffffffu, sumb, 2);
    const float nla = g_nl[bh * S_ + rowa];
    const float nlb = g_nl[bh * S_ + rowb];
    const float inva = 1.f / (fmaxf(fabsf(suma), nla) + EPS_);
    const float invb = 1.f / (fmaxf(fabsf(sumb), nlb) + EPS_);

    float sa = 0.f, sb = 0.f;
    #pragma unroll
    for (int n = 0; n < 16; ++n) {
        sa += hacc[n][0] + hacc[n][1];
        sb += hacc[n][2] + hacc[n][3];
    }
    sa *= inva; sb *= invb;
    sa += __shfl_xor_sync(0xffffffffu, sa, 1);
    sa += __shfl_xor_sync(0xffffffffu, sa, 2);
    sb += __shfl_xor_sync(0xffffffffu, sb, 1);
    sb += __shfl_xor_sync(0xffffffffu, sb, 2);
    const float mua = sa * (1.f / 128.f), mub = sb * (1.f / 128.f);

    float va = 0.f, vbv = 0.f;
    #pragma unroll
    for (int n = 0; n < 16; ++n) {
        float d0 = hacc[n][0] * inva - mua, d1 = hacc[n][1] * inva - mua;
        float d2 = hacc[n][2] * invb - mub, d3 = hacc[n][3] * invb - mub;
        va += d0 * d0 + d1 * d1;
        vbv += d2 * d2 + d3 * d3;
    }
    va += __shfl_xor_sync(0xffffffffu, va, 1);
    va += __shfl_xor_sync(0xffffffffu, va, 2);
    vbv += __shfl_xor_sync(0xffffffffu, vbv, 1);
    vbv += __shfl_xor_sync(0xffffffffu, vbv, 2);
    const float rsa = rsqrtf(va * (1.f / 128.f) + EPS_);
    const float rsb = rsqrtf(vbv * (1.f / 128.f) + EPS_);

    float* outa = out + ((size_t)(b * S_ + rowa)) * E_ + h * DH_;
    float* outb = out + ((size_t)(b * S_ + rowb)) * E_ + h * DH_;
    #pragma unroll
    for (int n = 0; n < 16; ++n) {
        const int d = n * 8 + 2 * tig;
        const float l0 = lnsc[h * DH_ + d], l1 = lnsc[h * DH_ + d + 1];
        float2 oa, ob;
        oa.x = (hacc[n][0] * inva - mua) * rsa * l0;
        oa.y = (hacc[n][1] * inva - mua) * rsa * l1;
        ob.x = (hacc[n][2] * invb - mub) * rsb * l0;
        ob.y = (hacc[n][3] * invb - mub) * rsb * l1;
        *(float2*)(outa + d) = oa;
        *(float2*)(outb + d) = ob;
    }
}

// =====================================================================
extern "C" void kernel_launch(void* const* d_in, const int* in_sizes, int n_in,
                              void* d_out, int out_size)
{
    const float* q  = (const float*)d_in[0];
    const float* k  = (const float*)d_in[1];
    const float* v  = (const float*)d_in[2];
    const float* Wi = (const float*)d_in[3];
    const float* bi = (const float*)d_in[4];
    const float* bf = (const float*)d_in[6];
    const float* Wf = (const float*)d_in[5];
    const float* ln = (const float*)d_in[7];
    float* out = (float*)d_out;

    cudaFuncSetAttribute(attn_k, cudaFuncAttributeMaxDynamicSharedMemorySize, SM_BYTES);

    gates_partial_k<<<dim3(32, NEC), 256>>>(q, k, v, Wi, Wf);
    scan_k<<<B_ * NH_, 1024>>>(bi, bf);
    attn_k<<<dim3(B_ * NH_, 8), 256, SM_BYTES>>>(q, k, v, ln, out);
}

// round 12
// speedup vs baseline: 1.3528x; 1.3528x over previous
#include <cuda_runtime.h>
#include <cuda_fp16.h>
#include <math.h>
#include <stdint.h>

#define B_   2
#define S_   1024
#define E_   2048
#define NH_  16
#define DH_  128
#define EPS_ 1e-6f
#define NEC  24
#define ECH  256          // 6144 / 24, 4 sub-tiles

#define FMA2(d, a, b)  asm("fma.rn.f32x2 %0, %1, %2, %0;" : "+l"(d) : "l"(a), "l"(b))
#define PACK2(d, x)    asm("mov.b64 %0, {%1, %1};" : "=l"(d) : "f"(x))

__device__ __forceinline__ void cpa16(uint32_t dst, const void* src) {
    asm volatile("cp.async.ca.shared.global [%0], [%1], 16;" :: "r"(dst), "l"(src));
}
__device__ __forceinline__ void cpa_commit() { asm volatile("cp.async.commit_group;"); }

// ---------------- warp-MMA helpers (sm_80-era PTX: safe under compute_103) ----------------
static __device__ __forceinline__ uint32_t pack_hf2(float x0, float x1) {
    uint32_t r; asm("cvt.rn.f16x2.f32 %0, %1, %2;" : "=r"(r) : "f"(x1), "f"(x0)); return r;
}
static __device__ __forceinline__ float lo_hf(uint32_t p) {
    return __half2float(__ushort_as_half((unsigned short)(p & 0xFFFFu)));
}
static __device__ __forceinline__ float hi_hf(uint32_t p) {
    return __half2float(__ushort_as_half((unsigned short)(p >> 16)));
}

#define LDSM4(r, a) \
    asm volatile("ldmatrix.sync.aligned.m8n8.x4.shared.b16 {%0,%1,%2,%3}, [%4];" \
        : "=r"((r)[0]), "=r"((r)[1]), "=r"((r)[2]), "=r"((r)[3]) : "r"(a))
#define LDSM4T(r, a) \
    asm volatile("ldmatrix.sync.aligned.m8n8.x4.trans.shared.b16 {%0,%1,%2,%3}, [%4];" \
        : "=r"((r)[0]), "=r"((r)[1]), "=r"((r)[2]), "=r"((r)[3]) : "r"(a))

static __device__ __forceinline__ void mma16816h(float* c, const uint32_t* a, const uint32_t* b) {
    asm volatile("mma.sync.aligned.m16n8k16.row.col.f32.f16.f16.f32 "
        "{%0,%1,%2,%3}, {%4,%5,%6,%7}, {%8,%9}, {%0,%1,%2,%3};"
        : "+f"(c[0]), "+f"(c[1]), "+f"(c[2]), "+f"(c[3])
        : "r"(a[0]), "r"(a[1]), "r"(a[2]), "r"(a[3]), "r"(b[0]), "r"(b[1]));
}

__device__ float g_part[2 * NEC * B_ * NH_ * S_];
__device__ float g_a [B_ * NH_ * S_];
__device__ float g_rm[B_ * NH_ * S_];
__device__ float g_nl[B_ * NH_ * S_];

// ============== Kernel 1: gates (R8 static double-buffer, NEC=24, known-good) ==============
__global__ __launch_bounds__(256) void gates_partial_k(
    const float* __restrict__ q, const float* __restrict__ k, const float* __restrict__ v,
    const float* __restrict__ Wi, const float* __restrict__ Wf)
{
    __shared__ float Xs[2][64 * 68];
    __shared__ float Ws[2][64 * 32];
    const int rt = blockIdx.x, ec = blockIdx.y;
    const int b = rt >> 4, s0 = (rt & 15) << 6, t = threadIdx.x;
    const int rgrp = t >> 3, hgrp = t & 7;

    auto pf = [&](int sub, int bufi) {
        const int e0 = ec * ECH + sub * 64;
        const float* xp = (e0 < E_) ? q : (e0 < 2 * E_) ? k : v;
        const int col0 = e0 & (E_ - 1);
        float* xd = Xs[bufi];
        float* wd = Ws[bufi];
        #pragma unroll
        for (int c = 0; c < 4; ++c) {
            int idx = t + c * 256, r = idx >> 4, q4 = (idx & 15) * 4;
            cpa16((uint32_t)__cvta_generic_to_shared(xd + r * 68 + q4),
                  xp + ((size_t)(b * S_ + s0 + r)) * E_ + col0 + q4);
        }
        #pragma unroll
        for (int c = 0; c < 2; ++c) {
            int idx = t + c * 256, ee = idx >> 3, cc = idx & 7, eg = e0 + ee;
            const float* src = (cc < 4) ? (Wi + eg * 16 + cc * 4)
                                        : (Wf + eg * 16 + (cc - 4) * 4);
            cpa16((uint32_t)__cvta_generic_to_shared(wd + ee * 32 + cc * 4), src);
        }
        cpa_commit();
    };

    unsigned long long acc2[2][2] = {};
    pf(0, 0);
    #pragma unroll 1
    for (int sub = 0; sub < 4; ++sub) {
        const int bufi = sub & 1;
        if (sub < 3) {
            pf(sub + 1, bufi ^ 1);
            asm volatile("cp.async.wait_group 1;");
        } else {
            asm volatile("cp.async.wait_group 0;");
        }
        __syncthreads();
        const float* xs = Xs[bufi];
        const float* ws = Ws[bufi];
        #pragma unroll 8
        for (int ee = 0; ee < 64; ++ee) {
            unsigned long long xp2[2];
            #pragma unroll
            for (int m = 0; m < 2; ++m) { float xv = xs[(rgrp * 2 + m) * 68 + ee]; PACK2(xp2[m], xv); }
            ulonglong2 wv = *(const ulonglong2*)(ws + ee * 32 + hgrp * 4);
            #pragma unroll
            for (int m = 0; m < 2; ++m) { FMA2(acc2[m][0], xp2[m], wv.x); FMA2(acc2[m][1], xp2[m], wv.y); }
        }
        __syncthreads();
    }
    #pragma unroll
    for (int m = 0; m < 2; ++m) {
        int s = s0 + rgrp * 2 + m;
        #pragma unroll
        for (int p = 0; p < 2; ++p) {
            float2 u = *(float2*)&acc2[m][p];
            #pragma unroll
            for (int hh = 0; hh < 2; ++hh) {
                int hcol = hgrp * 4 + p * 2 + hh;
                g_part[(((hcol >> 4) * NEC + ec) * (B_ * NH_) + b * NH_ + (hcol & 15)) * S_ + s] = hh ? u.y : u.x;
            }
        }
    }
}

// ============== Kernel 2: scans ==============
__global__ __launch_bounds__(1024, 1) void scan_k(const float* __restrict__ bi, const float* __restrict__ bf)
{
    __shared__ float buf[1024];
    const int bh = blockIdx.x, t = threadIdx.x, h = bh & 15;
    float ig = bi[h], fg = bf[h];
    #pragma unroll
    for (int ec = 0; ec < NEC; ++ec) {
        ig += g_part[((0 * NEC + ec) * (B_ * NH_) + bh) * S_ + t];
        fg += g_part[((1 * NEC + ec) * (B_ * NH_) + bh) * S_ + t];
    }
    float lf = fminf(fg, 0.f) - log1pf(expf(-fabsf(fg)));
    float x = lf;
    buf[t] = x; __syncthreads();
    for (int off = 1; off < 1024; off <<= 1) {
        float y = (t >= off) ? buf[t - off] : 0.f; __syncthreads();
        x += y; buf[t] = x; __syncthreads();
    }
    float cum = x, a = ig - cum;
    x = a; buf[t] = x; __syncthreads();
    for (int off = 1; off < 1024; off <<= 1) {
        float y = (t >= off) ? buf[t - off] : -3.4e38f; __syncthreads();
        x = fmaxf(x, y); buf[t] = x; __syncthreads();
    }
    g_a [bh * S_ + t] = a;
    g_rm[bh * S_ + t] = x;
    g_nl[bh * S_ + t] = expf(-(cum + x));
}

// ============== Kernel 3: HMMA fp16 2-term attention ==============
#define LDH  136
#define SM_QHI 0
#define SM_KHI 34816
#define SM_KLO 52224
#define SM_VHI 69632
#define SM_VLO 87040
#define SM_AS  104448
#define SM_RMS 104704
#define SM_ERS 105216
#define SM_WCS 105728
#define SM_BYTES 105984

__global__ __launch_bounds__(256, 1) void attn_k(
    const float* __restrict__ q, const float* __restrict__ k,
    const float* __restrict__ v, const float* __restrict__ lnsc,
    float* __restrict__ out)
{
    extern __shared__ char smc[];
    const uint32_t smb = (uint32_t)__cvta_generic_to_shared(smc);
    float* aS  = (float*)(smc + SM_AS);
    float* rmS = (float*)(smc + SM_RMS);
    float* erS = (float*)(smc + SM_ERS);
    float* wcS = (float*)(smc + SM_WCS);

    const int bh = blockIdx.x;
    const int b  = bh >> 4, h = bh & 15;
    const int ri = 7 - (int)blockIdx.y;      // heavy CTAs first
    const int i0 = ri << 7;
    const int t  = threadIdx.x;
    const int w  = t >> 5, lane = t & 31;
    const int gid = lane >> 2, tig = lane & 3;
    const float scale = 0.08838834764831845f;

    // ---- Q load: fold scale, fp16 (hi only) into padded row-major smem ----
    {
        const float* qb = q + ((size_t)(b * S_ + i0)) * E_ + h * DH_;
        #pragma unroll
        for (int it = 0; it < 16; ++it) {
            int idx = t + it * 256;
            int r = idx >> 5, d4 = (idx & 31) * 4;
            float4 x = *(const float4*)(qb + (size_t)r * E_ + d4);
            x.x *= scale; x.y *= scale; x.z *= scale; x.w *= scale;
            uint32_t h01 = pack_hf2(x.x, x.y), h23 = pack_hf2(x.z, x.w);
            uint32_t bo = (uint32_t)(r * LDH + d4) * 2;
            *(uint2*)(smc + SM_QHI + bo) = make_uint2(h01, h23);
        }
        if (t < 128) rmS[t] = g_rm[bh * S_ + i0 + t];
    }
    __syncthreads();

    // ---- cache Q fragments in registers (A-operand layout) ----
    uint32_t qh[8][4];
    {
        uint32_t rowq = (uint32_t)(w * 16 + (lane & 7) + 8 * ((lane >> 3) & 1));
        #pragma unroll
        for (int kk = 0; kk < 8; ++kk) {
            uint32_t off = (rowq * LDH + kk * 16 + 8 * (lane >> 4)) * 2;
            LDSM4(qh[kk], smb + SM_QHI + off);
        }
    }

    float hacc[16][4];
    #pragma unroll
    for (int n = 0; n < 16; ++n)
        #pragma unroll
        for (int e = 0; e < 4; ++e) hacc[n][e] = 0.f;
    float suma = 0.f, sumb = 0.f;

    const int rowa = i0 + w * 16 + gid;
    const int rowb = rowa + 8;
    const int nj = 2 * ri + 2;

    for (int jt = 0; jt < nj; ++jt) {
        const int j0 = jt << 6;
        __syncthreads();    // prev tile compute done before overwriting K/V/tables
        // ---- K,V tiles: fp16 hi/lo split ----
        {
            const float* kb = k + ((size_t)(b * S_ + j0)) * E_ + h * DH_;
            const float* vb = v + ((size_t)(b * S_ + j0)) * E_ + h * DH_;
            #pragma unroll
            for (int it = 0; it < 8; ++it) {
                int idx = t + it * 256;
                int r = idx >> 5, d4 = (idx & 31) * 4;
                uint32_t bo = (uint32_t)(r * LDH + d4) * 2;
                float4 x = *(const float4*)(kb + (size_t)r * E_ + d4);
                uint32_t h01 = pack_hf2(x.x, x.y), h23 = pack_hf2(x.z, x.w);
                uint32_t l01 = pack_hf2(x.x - lo_hf(h01), x.y - hi_hf(h01));
                uint32_t l23 = pack_hf2(x.z - lo_hf(h23), x.w - hi_hf(h23));
                *(uint2*)(smc + SM_KHI + bo) = make_uint2(h01, h23);
                *(uint2*)(smc + SM_KLO + bo) = make_uint2(l01, l23);
                float4 y = *(const float4*)(vb + (size_t)r * E_ + d4);
                uint32_t g01 = pack_hf2(y.x, y.y), g23 = pack_hf2(y.z, y.w);
                uint32_t m01 = pack_hf2(y.x - lo_hf(g01), y.y - hi_hf(g01));
                uint32_t m23 = pack_hf2(y.z - lo_hf(g23), y.w - hi_hf(g23));
                *(uint2*)(smc + SM_VHI + bo) = make_uint2(g01, g23);
                *(uint2*)(smc + SM_VLO + bo) = make_uint2(m01, m23);
            }
            if (t < 64) aS[t] = g_a[bh * S_ + j0 + t];
        }
        __syncthreads();
        // ---- exp tables ----
        if (t < 128) {
            float m0 = -3.4e38f;
            #pragma unroll 8
            for (int c = 0; c < 64; ++c) m0 = fmaxf(m0, aS[c]);
            if (t < 64) wcS[t] = __expf(aS[t] - m0);
            erS[t] = __expf(fminf(m0 - rmS[t], 80.f));
        }
        __syncthreads();

        // ---- QK: S = Qh·Kh + Qh·Kl ----
        float sacc[8][4];
        #pragma unroll
        for (int n = 0; n < 8; ++n)
            #pragma unroll
            for (int e = 0; e < 4; ++e) sacc[n][e] = 0.f;
        {
            uint32_t rowk = (uint32_t)((lane & 7) + 8 * (lane >> 4));
            uint32_t colk = (uint32_t)(8 * ((lane >> 3) & 1));
            #pragma unroll
            for (int kk = 0; kk < 8; ++kk) {
                #pragma unroll
                for (int np = 0; np < 4; ++np) {
                    uint32_t off = ((np * 16 + rowk) * LDH + kk * 16 + colk) * 2;
                    uint32_t bhf[4], blf[4];
                    LDSM4(bhf, smb + SM_KHI + off);
                    LDSM4(blf, smb + SM_KLO + off);
                    mma16816h(sacc[2 * np],     qh[kk], bhf);
                    mma16816h(sacc[2 * np],     qh[kk], blf);
                    mma16816h(sacc[2 * np + 1], qh[kk], bhf + 2);
                    mma16816h(sacc[2 * np + 1], qh[kk], blf + 2);
                }
            }
        }

        // ---- S -> P, causal mask, rowsums ----
        const float era = erS[w * 16 + gid];
        const float erb = erS[w * 16 + gid + 8];
        #pragma unroll
        for (int n = 0; n < 8; ++n) {
            const int cbase = n * 8 + 2 * tig;
            const int c0 = j0 + cbase, c1 = c0 + 1;
            const float w0 = wcS[cbase], w1 = wcS[cbase + 1];
            float p0 = (c0 <= rowa) ? sacc[n][0] * w0 * era : 0.f;
            float p1 = (c1 <= rowa) ? sacc[n][1] * w1 * era : 0.f;
            float p2 = (c0 <= rowb) ? sacc[n][2] * w0 * erb : 0.f;
            float p3 = (c1 <= rowb) ? sacc[n][3] * w1 * erb : 0.f;
            suma += p0 + p1; sumb += p2 + p3;
            sacc[n][0] = p0; sacc[n][1] = p1; sacc[n][2] = p2; sacc[n][3] = p3;
        }

        // ---- AV: H += Ph·Vh + Ph·Vl ----
        {
            uint32_t rowv = (uint32_t)((lane & 7) + 8 * ((lane >> 3) & 1));
            uint32_t colv = (uint32_t)(8 * (lane >> 4));
            #pragma unroll
            for (int kk = 0; kk < 4; ++kk) {
                uint32_t pah[4];
                pah[0] = pack_hf2(sacc[2*kk][0],   sacc[2*kk][1]);
                pah[1] = pack_hf2(sacc[2*kk][2],   sacc[2*kk][3]);
                pah[2] = pack_hf2(sacc[2*kk+1][0], sacc[2*kk+1][1]);
                pah[3] = pack_hf2(sacc[2*kk+1][2], sacc[2*kk+1][3]);
                #pragma unroll
                for (int np = 0; np < 8; ++np) {
                    uint32_t off = ((kk * 16 + rowv) * LDH + np * 16 + colv) * 2;
                    uint32_t bvh[4], bvl[4];
                    LDSM4T(bvh, smb + SM_VHI + off);
                    LDSM4T(bvl, smb + SM_VLO + off);
                    mma16816h(hacc[2 * np],     pah, bvh);
                    mma16816h(hacc[2 * np],     pah, bvl);
                    mma16816h(hacc[2 * np + 1], pah, bvh + 2);
                    mma16816h(hacc[2 * np + 1], pah, bvl + 2);
                }
            }
        }
    }

    // ---- epilogue ----
    suma += __shfl_xor_sync(0xffffffffu, suma, 1);
    suma += __shfl_xor_sync(0xffffffffu, suma, 2);
    sumb += __shfl_xor_sync(0xffffffffu, sumb, 1);
    sumb += __shfl_xor_sync(0xffffffffu, sumb, 2);
    const float nla = g_nl[bh * S_ + rowa];
    const float nlb = g_nl[bh * S_ + rowb];
    const float inva = 1.f / (fmaxf(fabsf(suma), nla) + EPS_);
    const float invb = 1.f / (fmaxf(fabsf(sumb), nlb) + EPS_);

    float sa = 0.f, sb = 0.f;
    #pragma unroll
    for (int n = 0; n < 16; ++n) {
        sa += hacc[n][0] + hacc[n][1];
        sb += hacc[n][2] + hacc[n][3];
    }
    sa *= inva; sb *= invb;
    sa += __shfl_xor_sync(0xffffffffu, sa, 1);
    sa += __shfl_xor_sync(0xffffffffu, sa, 2);
    sb += __shfl_xor_sync(0xffffffffu, sb, 1);
    sb += __shfl_xor_sync(0xffffffffu, sb, 2);
    const float mua = sa * (1.f / 128.f), mub = sb * (1.f / 128.f);

    float va = 0.f, vbv = 0.f;
    #pragma unroll
    for (int n = 0; n < 16; ++n) {
        float d0 = hacc[n][0] * inva - mua, d1 = hacc[n][1] * inva - mua;
        float d2 = hacc[n][2] * invb - mub, d3 = hacc[n][3] * invb - mub;
        va += d0 * d0 + d1 * d1;
        vbv += d2 * d2 + d3 * d3;
    }
    va += __shfl_xor_sync(0xffffffffu, va, 1);
    va += __shfl_xor_sync(0xffffffffu, va, 2);
    vbv += __shfl_xor_sync(0xffffffffu, vbv, 1);
    vbv += __shfl_xor_sync(0xffffffffu, vbv, 2);
    const float rsa = rsqrtf(va * (1.f / 128.f) + EPS_);
    const float rsb = rsqrtf(vbv * (1.f / 128.f) + EPS_);

    float* outa = out + ((size_t)(b * S_ + rowa)) * E_ + h * DH_;
    float* outb = out + ((size_t)(b * S_ + rowb)) * E_ + h * DH_;
    #pragma unroll
    for (int n = 0; n < 16; ++n) {
        const int d = n * 8 + 2 * tig;
        const float l0 = lnsc[h * DH_ + d], l1 = lnsc[h * DH_ + d + 1];
        float2 oa, ob;
        oa.x = (hacc[n][0] * inva - mua) * rsa * l0;
        oa.y = (hacc[n][1] * inva - mua) * rsa * l1;
        ob.x = (hacc[n][2] * invb - mub) * rsb * l0;
        ob.y = (hacc[n][3] * invb - mub) * rsb * l1;
        *(float2*)(outa + d) = oa;
        *(float2*)(outb + d) = ob;
    }
}

// =====================================================================
extern "C" void kernel_launch(void* const* d_in, const int* in_sizes, int n_in,
                              void* d_out, int out_size)
{
    const float* q  = (const float*)d_in[0];
    const float* k  = (const float*)d_in[1];
    const float* v  = (const float*)d_in[2];
    const float* Wi = (const float*)d_in[3];
    const float* bi = (const float*)d_in[4];
    const float* Wf = (const float*)d_in[5];
    const float* bf = (const float*)d_in[6];
    const float* ln = (const float*)d_in[7];
    float* out = (float*)d_out;

    cudaFuncSetAttribute(attn_k, cudaFuncAttributeMaxDynamicSharedMemorySize, SM_BYTES);

    gates_partial_k<<<dim3(32, NEC), 256>>>(q, k, v, Wi, Wf);
    scan_k<<<B_ * NH_, 1024>>>(bi, bf);
    attn_k<<<dim3(B_ * NH_, 8), 256, SM_BYTES>>>(q, k, v, ln, out);
}